// round 16
// baseline (speedup 1.0000x reference)
#include <cuda_runtime.h>
#include <stdint.h>
#include <math.h>

#define Pw    7
#define PP    49
#define HEADS 8
#define DH    32
#define INNER 256
#define Cc    128
#define Bb    32
#define HW    56
#define WINS  2048
#define MROWS (WINS*PP)    // 100352

static __device__ float g_xw  [(size_t)MROWS * Cc];
static __device__ float g_qkv [(size_t)MROWS * 3 * INNER];
static __device__ float g_omid[(size_t)MROWS * INNER];
static __device__ float g_wqkv_r[768 * 128];   // [n][k] original layout, tf32-rounded
static __device__ float g_wout_r[128 * 256];   // [n][k] original layout, tf32-rounded
static __device__ float g_mask [4 * 49 * 56];
static __device__ float g_attn_dump[(size_t)WINS * HEADS * PP * PP];
static __device__ float g_o_dump  [(size_t)Bb * Cc * HW * HW];

__device__ __forceinline__ unsigned int f2tf32(float f) {
    unsigned int u; asm("cvt.rna.tf32.f32 %0, %1;" : "=r"(u) : "f"(f)); return u;
}
__device__ __forceinline__ float tf32r(float f) { return __uint_as_float(f2tf32(f)); }

__device__ __forceinline__ void mma_tf32(float c[4],
    unsigned int a0, unsigned int a1, unsigned int a2, unsigned int a3,
    unsigned int b0, unsigned int b1)
{
    asm volatile(
        "mma.sync.aligned.m16n8k8.row.col.f32.tf32.tf32.f32 "
        "{%0,%1,%2,%3}, {%4,%5,%6,%7}, {%8,%9}, {%0,%1,%2,%3};"
        : "+f"(c[0]), "+f"(c[1]), "+f"(c[2]), "+f"(c[3])
        : "r"(a0), "r"(a1), "r"(a2), "r"(a3), "r"(b0), "r"(b1));
}

__device__ __forceinline__ void ldsm4(unsigned int& r0, unsigned int& r1,
                                      unsigned int& r2, unsigned int& r3,
                                      unsigned int addr)
{
    asm volatile("ldmatrix.sync.aligned.m8n8.x4.shared.b16 {%0,%1,%2,%3}, [%4];"
        : "=r"(r0), "=r"(r1), "=r"(r2), "=r"(r3) : "r"(addr));
}
__device__ __forceinline__ void ldsm2(unsigned int& r0, unsigned int& r1,
                                      unsigned int addr)
{
    asm volatile("ldmatrix.sync.aligned.m8n8.x2.shared.b16 {%0,%1}, [%2];"
        : "=r"(r0), "=r"(r1) : "r"(addr));
}

__device__ __forceinline__ void cp16(unsigned int saddr, const void* gaddr) {
    asm volatile("cp.async.cg.shared.global [%0], [%1], 16;" :: "r"(saddr), "l"(gaddr));
}
__device__ __forceinline__ void cp_commit() { asm volatile("cp.async.commit_group;"); }
__device__ __forceinline__ void cp_wait1()  { asm volatile("cp.async.wait_group 1;"); }
__device__ __forceinline__ void cp_wait0()  { asm volatile("cp.async.wait_group 0;"); }

__device__ __forceinline__ float4 tf32r4(float4 v) {
    return make_float4(tf32r(v.x), tf32r(v.y), tf32r(v.z), tf32r(v.w));
}
__device__ __forceinline__ float4 tf32r4s(float4 v, float s) {
    return make_float4(tf32r(v.x * s), tf32r(v.y * s), tf32r(v.z * s), tf32r(v.w * s));
}

// ---------------------------------------------------------------------------
// Kernel 0: tf32-round weights (original [n][k] layout) + bias+mask tables.
// ---------------------------------------------------------------------------
__global__ void prep_wm(const float* __restrict__ wq, const float* __restrict__ wo,
                        const float* __restrict__ pos)
{
    int idx = blockIdx.x * 256 + threadIdx.x;
    if (idx < 768 * 128) g_wqkv_r[idx] = tf32r(wq[idx]);
    int i2 = idx - 768 * 128;
    if (i2 >= 0 && i2 < 128 * 256) g_wout_r[i2] = tf32r(wo[i2]);
    if (idx < 4 * 49 * 56) {
        int cls = idx / (49 * 56);
        int rem = idx - cls * 49 * 56;
        int i = rem / 56, j = rem - i * 56;
        float val;
        if (j >= 49) {
            val = -1e30f;
        } else {
            int xi = i / Pw, yi = i - xi * Pw;
            int xj = j / Pw, yj = j - xj * Pw;
            val = pos[(xj - xi + 6) * 13 + (yj - yi + 6)];
            if ((cls & 1) && ((i >= 28) != (j >= 28))) val = -1e30f;
            if ((cls & 2) && ((yi >= 4) != (yj >= 4))) val = -1e30f;
        }
        g_mask[idx] = val;
    }
}

// ---------------------------------------------------------------------------
// Kernel 1: gather (roll -3,-3 + window partition) -> g_xw, tf32-rounded.
// ---------------------------------------------------------------------------
__global__ void gather_x(const float* __restrict__ x)
{
    __shared__ float sm[128][65];
    const int b  = blockIdx.x / 49;
    const int p0 = (blockIdx.x - b * 49) * 64;
    const int tid = threadIdx.x;

    for (int i = tid; i < 128 * 64; i += 256) {
        int c = i >> 6, p = i & 63;
        sm[c][p] = x[((size_t)b * 128 + c) * 3136 + p0 + p];
    }
    __syncthreads();
    for (int i = tid; i < 64 * 128; i += 256) {
        int p = i >> 7, c = i & 127;
        int pix = p0 + p;
        int h = pix / HW, w = pix - h * HW;
        int hs = h - 3; if (hs < 0) hs += HW;
        int ws = w - 3; if (ws < 0) ws += HW;
        int win = b * 64 + (hs / Pw) * 8 + (ws / Pw);
        int t   = (hs % Pw) * Pw + (ws % Pw);
        g_xw[((size_t)win * PP + t) * Cc + c] = tf32r(sm[c][p]);
    }
}

// ---------------------------------------------------------------------------
// Kernel 2: QKV GEMM, ldmatrix fragments, 3-stage cp.async, 512 thr
// (unchanged from R15 pass).
// ---------------------------------------------------------------------------
__global__ void __launch_bounds__(512, 2) qkv_gemm_tc()
{
    __shared__ float As[3][128][20];
    __shared__ float Bs[3][128][20];
    const unsigned int STG = 2560 * 4;

    const int tid  = threadIdx.x;
    const int bm   = blockIdx.y * 128;
    const int bn   = blockIdx.x * 128;
    const int lane = tid & 31, wid = tid >> 5;
    const int wm   = (wid & 3) * 32, wn = (wid >> 2) * 32;
    const int qr   = lane >> 2, ql = lane & 3;

    const int fr = tid >> 2, fq = (tid & 3) * 4;
    const float* agp = g_xw     + (size_t)(bm + fr) * 128 + fq;
    const float* bgp = g_wqkv_r + (size_t)(bn + fr) * 128 + fq;

    const unsigned int aSm = (unsigned int)__cvta_generic_to_shared(&As[0][fr][fq]);
    const unsigned int bSm = (unsigned int)__cvta_generic_to_shared(&Bs[0][fr][fq]);
    const unsigned int aBase = (unsigned int)__cvta_generic_to_shared(As);
    const unsigned int bBase = (unsigned int)__cvta_generic_to_shared(Bs);

    const unsigned int aoff = ((wm + (lane & 15)) * 20 + 4 * (lane >> 4)) * 4;
    const unsigned int boff = (((lane & 7) + 8 * (lane >> 4) + wn) * 20
                               + 4 * ((lane >> 3) & 1)) * 4;

    float acc[2][4][4];
    #pragma unroll
    for (int i = 0; i < 2; i++)
        #pragma unroll
        for (int j = 0; j < 4; j++)
            #pragma unroll
            for (int c = 0; c < 4; c++) acc[i][j][c] = 0.f;

    #pragma unroll
    for (int s = 0; s < 2; s++) {
        const int k0 = s * 16;
        cp16(aSm + s * STG, agp + k0);
        cp16(bSm + s * STG, bgp + k0);
        cp_commit();
    }

    #pragma unroll
    for (int ks = 0; ks < 8; ks++) {
        if (ks < 7) cp_wait1(); else cp_wait0();
        __syncthreads();
        const int st = ks % 3;
        #pragma unroll
        for (int k8 = 0; k8 < 16; k8 += 8) {
            unsigned int af[2][4], bf[4][2];
            ldsm4(af[0][0], af[0][1], af[0][2], af[0][3],
                  aBase + st * STG + aoff + k8 * 4);
            ldsm4(af[1][0], af[1][1], af[1][2], af[1][3],
                  aBase + st * STG + aoff + (320 + k8) * 4);
            ldsm4(bf[0][0], bf[0][1], bf[1][0], bf[1][1],
                  bBase + st * STG + boff + k8 * 4);
            ldsm4(bf[2][0], bf[2][1], bf[3][0], bf[3][1],
                  bBase + st * STG + boff + (320 + k8) * 4);
            #pragma unroll
            for (int mt = 0; mt < 2; mt++)
                #pragma unroll
                for (int nt = 0; nt < 4; nt++)
                    mma_tf32(acc[mt][nt], af[mt][0], af[mt][1], af[mt][2], af[mt][3],
                             bf[nt][0], bf[nt][1]);
        }
        __syncthreads();
        if (ks + 2 < 8) {
            const int snew = (ks + 2) % 3;
            const int k0 = (ks + 2) * 16;
            cp16(aSm + snew * STG, agp + k0);
            cp16(bSm + snew * STG, bgp + k0);
            cp_commit();
        }
    }

    #pragma unroll
    for (int mt = 0; mt < 2; mt++) {
        int r0 = bm + wm + mt * 16 + qr;
        #pragma unroll
        for (int nt = 0; nt < 4; nt++) {
            int c = bn + wn + nt * 8 + ql * 2;
            *(float2*)&g_qkv[(size_t)r0 * 768 + c] =
                make_float2(acc[mt][nt][0], acc[mt][nt][1]);
            *(float2*)&g_qkv[(size_t)(r0 + 8) * 768 + c] =
                make_float2(acc[mt][nt][2], acc[mt][nt][3]);
        }
    }
}

// ---------------------------------------------------------------------------
// Kernel 3: TC attention, TWO heads per block (256 thr, warps 0-3 / 4-7).
// Per-head logic identical to R15; loads are 256B-contiguous per row.
// Dynamic smem layout (floats):
//   usm[2] @ 0      (2 x 2940)  Q [49][36] then P [49][60]
//   ksm[2] @ 5880   (2 x 2016)  K [56][36]
//   vsm[2] @ 9912   (2 x 1920)  V^T [32][60]
// ---------------------------------------------------------------------------
#define ATTN_SMEM_FLOATS (5880 + 2 * 2016 + 2 * 1920)   // 13752 -> 55008 B
#define QSM(r,c) usm[(r) * 36 + (c)]
#define SSM(r,c) usm[(r) * 60 + (c)]

__global__ void __launch_bounds__(256, 4) attn_tc_kernel(float* __restrict__ attn_out)
{
    extern __shared__ float smp[];

    const int blk  = blockIdx.x;       // win*4 + hp
    const int win  = blk >> 2;
    const int hp   = blk & 3;          // head pair index
    const int wl   = win & 63;
    const int cls  = ((wl >= 56) ? 1 : 0) | (((wl == 55) || (wl == 63)) ? 2 : 0);

    const int tid  = threadIdx.x;
    const int lane = tid & 31;
    const int warp = tid >> 5;
    const int pg   = warp >> 2;        // head within pair (0/1)
    const int wpg  = warp & 3;
    const int gtid = tid & 127;
    const int wm   = wpg * 16;
    const int qr   = lane >> 2;
    const int ql   = lane & 3;

    float* usm = smp + pg * 2940;
    float* ksm = smp + 5880 + pg * 2016;
    float* vsm = smp + 9912 + pg * 1920;

    const float* qkvb = g_qkv + (size_t)win * PP * 768 + hp * 64;
    const float scale = 0.1767766952966369f;

    // zero pads for BOTH heads (block-wide loops)
    for (int idx = tid; idx < 2 * 15 * 36; idx += 256) {       // Q rows 49..63
        int g = idx / 540, r = idx - g * 540;
        smp[g * 2940 + (49 + r / 36) * 36 + r % 36] = 0.f;
    }
    for (int idx = tid; idx < 2 * 7 * 32; idx += 256) {        // K rows 49..55
        int g = idx / 224, r = idx - g * 224;
        smp[5880 + g * 2016 + (49 + (r >> 5)) * 36 + (r & 31)] = 0.f;
    }
    for (int idx = tid; idx < 2 * 32 * 11; idx += 256) {       // V^T cols 49..59
        int g = idx / 352, r = idx - g * 352;
        smp[9912 + g * 1920 + (r / 11) * 60 + 49 + (r % 11)] = 0.f;
    }

    // fused load: 49 rows x 16 float4 per matrix-pair (256B contiguous)
    for (int idx = tid; idx < PP * 16; idx += 256) {
        const int j  = idx >> 4;
        const int f4 = idx & 15;
        const int g  = f4 >> 3;
        const int d  = (f4 & 7) * 4;
        const float* row = qkvb + (size_t)j * 768 + f4 * 4;
        float4 qv = *(const float4*)(row);
        float4 kv = *(const float4*)(row + 256);
        float4 vv = *(const float4*)(row + 512);
        float* us = smp + g * 2940;
        float* ks = smp + 5880 + g * 2016;
        float* vs = smp + 9912 + g * 1920;
        *(float4*)&us[j * 36 + d] = tf32r4s(qv, scale);
        *(float4*)&ks[j * 36 + d] = tf32r4(kv);
        vs[(d + 0) * 60 + j] = tf32r(vv.x);
        vs[(d + 1) * 60 + j] = tf32r(vv.y);
        vs[(d + 2) * 60 + j] = tf32r(vv.z);
        vs[(d + 3) * 60 + j] = tf32r(vv.w);
    }

    const int rA = wm + qr, rB = rA + 8;
    const bool vA = (rA < PP), vB = (rB < PP);

    // init S accumulators from mask table
    const float* mrowA = g_mask + cls * (49 * 56) + (vA ? rA : 48) * 56;
    const float* mrowB = g_mask + cls * (49 * 56) + (vB ? rB : 48) * 56;
    float s[7][4];
    #pragma unroll
    for (int nt = 0; nt < 7; nt++) {
        const int j0 = nt * 8 + ql * 2;
        float2 ma = *(const float2*)(mrowA + j0);
        float2 mb = *(const float2*)(mrowB + j0);
        s[nt][0] = ma.x; s[nt][1] = ma.y;
        s[nt][2] = mb.x; s[nt][3] = mb.y;
    }
    __syncthreads();

    const unsigned int usmB = (unsigned int)__cvta_generic_to_shared(usm);
    const unsigned int ksmB = (unsigned int)__cvta_generic_to_shared(ksm);
    const unsigned int vsmB = (unsigned int)__cvta_generic_to_shared(vsm);

    // ---- S = (Q*scale) @ K^T + mask ----
    const unsigned int qaoff = ((wm + (lane & 15)) * 36 + 4 * (lane >> 4)) * 4;
    const unsigned int kboff  = (((lane & 7) + 8 * (lane >> 4)) * 36
                                 + 4 * ((lane >> 3) & 1)) * 4;
    const unsigned int kboff2 = ((lane & 7) * 36 + 4 * ((lane >> 3) & 1)) * 4;

    #pragma unroll
    for (int ks = 0; ks < 4; ks++) {
        const int k8 = ks * 8;
        unsigned int a[4], b[7][2];
        ldsm4(a[0], a[1], a[2], a[3], usmB + qaoff + k8 * 4);
        ldsm4(b[0][0], b[0][1], b[1][0], b[1][1], ksmB + kboff  + (k8) * 4);
        ldsm4(b[2][0], b[2][1], b[3][0], b[3][1], ksmB + kboff  + (16 * 36 + k8) * 4);
        ldsm4(b[4][0], b[4][1], b[5][0], b[5][1], ksmB + kboff  + (32 * 36 + k8) * 4);
        ldsm2(b[6][0], b[6][1],                   ksmB + kboff2 + (48 * 36 + k8) * 4);
        #pragma unroll
        for (int nt = 0; nt < 7; nt++)
            mma_tf32(s[nt], a[0], a[1], a[2], a[3], b[nt][0], b[nt][1]);
    }

    __syncthreads();   // Q reads done; usm becomes P storage

    // ---- softmax on fragments ----
    {
        float mA = -1e30f, mB = -1e30f;
        #pragma unroll
        for (int nt = 0; nt < 7; nt++) {
            mA = fmaxf(mA, fmaxf(s[nt][0], s[nt][1]));
            mB = fmaxf(mB, fmaxf(s[nt][2], s[nt][3]));
        }
        mA = fmaxf(mA, __shfl_xor_sync(0xffffffffu, mA, 1));
        mA = fmaxf(mA, __shfl_xor_sync(0xffffffffu, mA, 2));
        mB = fmaxf(mB, __shfl_xor_sync(0xffffffffu, mB, 1));
        mB = fmaxf(mB, __shfl_xor_sync(0xffffffffu, mB, 2));

        float sA = 0.f, sB = 0.f;
        #pragma unroll
        for (int nt = 0; nt < 7; nt++) {
            s[nt][0] = __expf(s[nt][0] - mA);
            s[nt][1] = __expf(s[nt][1] - mA);
            s[nt][2] = __expf(s[nt][2] - mB);
            s[nt][3] = __expf(s[nt][3] - mB);
            sA += s[nt][0] + s[nt][1];
            sB += s[nt][2] + s[nt][3];
        }
        sA += __shfl_xor_sync(0xffffffffu, sA, 1);
        sA += __shfl_xor_sync(0xffffffffu, sA, 2);
        sB += __shfl_xor_sync(0xffffffffu, sB, 1);
        sB += __shfl_xor_sync(0xffffffffu, sB, 2);
        const float iAu = 1.0f / sA, iBu = 1.0f / sB;

        #pragma unroll
        for (int nt = 0; nt < 7; nt++) {
            int j0 = nt * 8 + ql * 2;
            if (vA) *(float2*)&SSM(rA, j0) = make_float2(s[nt][0] * iAu, s[nt][1] * iAu);
            if (vB) *(float2*)&SSM(rB, j0) = make_float2(s[nt][2] * iBu, s[nt][3] * iBu);
        }
    }
    // zero P pad cols 49..55 (per head, its own 128 threads)
    for (int idx = gtid; idx < 49 * 7; idx += 128)
        SSM(idx / 7, 49 + idx % 7) = 0.f;
    __syncthreads();

    // coalesced attn write (fp32), each head-group writes its head
    float* aout = attn_out + ((size_t)(win * 8 + hp * 2 + pg)) * (PP * PP);
    for (int idx = gtid; idx < PP * PP; idx += 128) {
        int r = idx / PP;
        aout[idx] = SSM(r, idx - r * PP);
    }

    // ---- O = P @ V ----
    int prow = wm + (lane & 15); if (prow > 48) prow = 48;
    const unsigned int paoff = (prow * 60 + 4 * (lane >> 4)) * 4;
    const unsigned int vboff = (((lane & 7) + 8 * (lane >> 4)) * 60
                                + 4 * ((lane >> 3) & 1)) * 4;

    float o[4][4];
    #pragma unroll
    for (int nt = 0; nt < 4; nt++)
        #pragma unroll
        for (int c = 0; c < 4; c++) o[nt][c] = 0.f;

    #pragma unroll
    for (int ks = 0; ks < 7; ks++) {
        const int k8 = ks * 8;
        unsigned int ar[4], a[4], b[4][2];
        ldsm4(ar[0], ar[1], ar[2], ar[3], usmB + paoff + k8 * 4);
        a[0] = f2tf32(__uint_as_float(ar[0]));
        a[1] = f2tf32(__uint_as_float(ar[1]));
        a[2] = f2tf32(__uint_as_float(ar[2]));
        a[3] = f2tf32(__uint_as_float(ar[3]));
        ldsm4(b[0][0], b[0][1], b[1][0], b[1][1], vsmB + vboff + k8 * 4);
        ldsm4(b[2][0], b[2][1], b[3][0], b[3][1], vsmB + vboff + (16 * 60 + k8) * 4);
        #pragma unroll
        for (int nt = 0; nt < 4; nt++)
            mma_tf32(o[nt], a[0], a[1], a[2], a[3], b[nt][0], b[nt][1]);
    }

    float* ob = g_omid + (size_t)win * PP * INNER + (hp * 2 + pg) * 32;
    #pragma unroll
    for (int nt = 0; nt < 4; nt++) {
        int c = nt * 8 + ql * 2;
        if (vA)
            *(float2*)&ob[(size_t)rA * INNER + c] =
                make_float2(tf32r(o[nt][0]), tf32r(o[nt][1]));
        if (vB)
            *(float2*)&ob[(size_t)rB * INNER + c] =
                make_float2(tf32r(o[nt][2]), tf32r(o[nt][3]));
    }
}

// ---------------------------------------------------------------------------
// Kernel 4: out GEMM, ldmatrix fragments, 3-stage cp.async, 512 thr,
// staged coalesced scatter (unchanged from R15 pass).
// ---------------------------------------------------------------------------
#define OSTG(r,c)   smbuf[(r) * 133 + (c)]

__global__ void __launch_bounds__(512, 2) out_gemm_tc(const float* __restrict__ b_out,
                                                      float* __restrict__ out)
{
    __shared__ float smbuf[17024];
    const unsigned int STG = 2560 * 4;

    const int tid  = threadIdx.x;
    const int bm   = blockIdx.y * 128;
    const int lane = tid & 31, wid = tid >> 5;
    const int wm   = (wid & 3) * 32, wn = (wid >> 2) * 32;
    const int qr   = lane >> 2, ql = lane & 3;

    const int fr = tid >> 2, fq = (tid & 3) * 4;
    const float* agp = g_omid   + (size_t)(bm + fr) * INNER + fq;
    const float* bgp = g_wout_r + (size_t)fr * 256 + fq;

    const unsigned int base = (unsigned int)__cvta_generic_to_shared(smbuf);
    const unsigned int aSm = base + (fr * 20 + fq) * 4;
    const unsigned int bSm = base + (7680 + fr * 20 + fq) * 4;

    const unsigned int aAbs = base + ((wm + (lane & 15)) * 20 + 4 * (lane >> 4)) * 4;
    const unsigned int bAbs = base + (7680 + ((lane & 7) + 8 * (lane >> 4) + wn) * 20
                                      + 4 * ((lane >> 3) & 1)) * 4;

    float acc[2][4][4];
    #pragma unroll
    for (int i = 0; i < 2; i++)
        #pragma unroll
        for (int j = 0; j < 4; j++)
            #pragma unroll
            for (int c = 0; c < 4; c++) acc[i][j][c] = 0.f;

    #pragma unroll
    for (int s = 0; s < 2; s++) {
        const int k0 = s * 16;
        cp16(aSm + s * STG, agp + k0);
        cp16(bSm + s * STG, bgp + k0);
        cp_commit();
    }

    #pragma unroll
    for (int ks = 0; ks < 16; ks++) {
        if (ks < 15) cp_wait1(); else cp_wait0();
        __syncthreads();
        const int st = ks % 3;
        #pragma unroll
        for (int k8 = 0; k8 < 16; k8 += 8) {
            unsigned int af[2][4], bf[4][2];
            ldsm4(af[0][0], af[0][1], af[0][2], af[0][3],
                  aAbs + st * STG + k8 * 4);
            ldsm4(af[1][0], af[1][1], af[1][2], af[1][3],
                  aAbs + st * STG + (320 + k8) * 4);
            ldsm4(bf[0][0], bf[0][1], bf[1][0], bf[1][1],
                  bAbs + st * STG + k8 * 4);
            ldsm4(bf[2][0], bf[2][1], bf[3][0], bf[3][1],
                  bAbs + st * STG + (320 + k8) * 4);
            #pragma unroll
            for (int mt = 0; mt < 2; mt++)
                #pragma unroll
                for (int nt = 0; nt < 4; nt++)
                    mma_tf32(acc[mt][nt], af[mt][0], af[mt][1], af[mt][2], af[mt][3],
                             bf[nt][0], bf[nt][1]);
        }
        __syncthreads();
        if (ks + 2 < 16) {
            const int snew = (ks + 2) % 3;
            const int k0 = (ks + 2) * 16;
            cp16(aSm + snew * STG, agp + k0);
            cp16(bSm + snew * STG, bgp + k0);
            cp_commit();
        }
    }

    __syncthreads();
    #pragma unroll
    for (int mt = 0; mt < 2; mt++) {
        #pragma unroll
        for (int half = 0; half < 2; half++) {
            int r = wm + mt * 16 + qr + half * 8;
            #pragma unroll
            for (int nt = 0; nt < 4; nt++) {
                int c = wn + nt * 8 + ql * 2;
                OSTG(r, c)     = acc[mt][nt][half * 2 + 0] + b_out[c];
                OSTG(r, c + 1) = acc[mt][nt][half * 2 + 1] + b_out[c + 1];
            }
        }
    }
    __syncthreads();

    for (int idx = tid; idx < 128 * 128; idx += 512) {
        int c  = idx >> 7;
        int sr = idx & 127;
        int r  = bm + sr;
        int win = r / PP;
        int t   = r - win * PP;
        int b   = win >> 6;
        int wl  = win & 63;
        int i1  = wl >> 3, i2 = wl & 7;
        int xx  = t / Pw,  yy = t - (t / Pw) * Pw;
        int h = i1 * Pw + xx + 3; if (h >= HW) h -= HW;
        int w = i2 * Pw + yy + 3; if (w >= HW) w -= HW;
        out[((size_t)b * 128 + c) * 3136 + h * HW + w] = OSTG(sr, c);
    }
}

// ---------------------------------------------------------------------------
extern "C" void kernel_launch(void* const* d_in, const int* in_sizes, int n_in,
                              void* d_out, int out_size)
{
    const float* x      = (const float*)d_in[0];
    const float* w_qkv  = (const float*)d_in[1];
    const float* w_out  = (const float*)d_in[2];
    const float* b_out  = (const float*)d_in[3];
    const float* pos    = (const float*)d_in[4];

    const long long O_ELEMS = (long long)Bb * Cc * HW * HW;
    const long long A_ELEMS = (long long)WINS * HEADS * PP * PP;

    float* outp = (float*)d_out;
    float* o_ptr;
    float* attn_ptr;

    if ((long long)out_size >= O_ELEMS + A_ELEMS) {
        o_ptr    = outp;
        attn_ptr = outp + O_ELEMS;
    } else if ((long long)out_size == A_ELEMS) {
        attn_ptr = outp;
        cudaGetSymbolAddress((void**)&o_ptr, g_o_dump);
    } else {
        o_ptr = outp;
        cudaGetSymbolAddress((void**)&attn_ptr, g_attn_dump);
    }

    static int smem_set = 0;
    if (!smem_set) {
        cudaFuncSetAttribute(attn_tc_kernel,
                             cudaFuncAttributeMaxDynamicSharedMemorySize,
                             ATTN_SMEM_FLOATS * 4);
        smem_set = 1;
    }

    prep_wm<<<512, 256>>>(w_qkv, w_out, pos);
    gather_x<<<Bb * 49, 256>>>(x);
    qkv_gemm_tc<<<dim3(768 / 128, MROWS / 128), 512>>>();
    attn_tc_kernel<<<WINS * 4, 256, ATTN_SMEM_FLOATS * 4>>>(attn_ptr);
    out_gemm_tc<<<dim3(1, MROWS / 128), 512>>>(b_out, o_ptr);
}